// round 11
// baseline (speedup 1.0000x reference)
#include <cuda_runtime.h>
#include <math.h>
#include <stdint.h>

#define SEQ   512
#define BATCH 128
#define INPD  256
#define HID   1024
#define G4    4096
#define TB    (SEQ*BATCH)   // 65536 rows

// ---- scratch (allocation-free: device globals) ----
__device__ float g_xproj[(size_t)TB * G4];   // 1 GiB: [T*B, 4H]
__device__ float g_hs[(size_t)TB * HID];     // 256 MiB: h per timestep (fp32)
__device__ float g_c[2][BATCH * HID];        // ping-pong cell state
// tf32-valued fp32 planes (split once, read raw in mainloop):
__device__ __align__(16) float g_whh_pl[2][(size_t)G4 * HID];   // Whh hi/lo
__device__ __align__(16) float g_h_pl[2][2][BATCH * HID];       // h hi/lo, ping-pong

__device__ __forceinline__ float sigmoidf_(float x) { return 1.0f / (1.0f + expf(-x)); }

// ============================================================================
// tf32 mma helpers (m16n8k8, 3xTF32 fp32-emulation) + cp.async
// ============================================================================
__device__ __forceinline__ unsigned smaddr_(const void* p) {
    return (unsigned)__cvta_generic_to_shared(p);
}
__device__ __forceinline__ unsigned cvt_tf32(float x) {
    unsigned r;
    asm("cvt.rna.tf32.f32 %0, %1;" : "=r"(r) : "f"(x));
    return r;
}
__device__ __forceinline__ void split_tf32(float x, unsigned& hi, unsigned& lo) {
    hi = cvt_tf32(x);
    lo = cvt_tf32(x - __uint_as_float(hi));
}
__device__ __forceinline__ void mma_tf32(float* c, const unsigned* a, const unsigned* b) {
    asm volatile("mma.sync.aligned.m16n8k8.row.col.f32.tf32.tf32.f32 "
        "{%0,%1,%2,%3},{%4,%5,%6,%7},{%8,%9},{%0,%1,%2,%3};"
        : "+f"(c[0]), "+f"(c[1]), "+f"(c[2]), "+f"(c[3])
        : "r"(a[0]), "r"(a[1]), "r"(a[2]), "r"(a[3]), "r"(b[0]), "r"(b[1]));
}
__device__ __forceinline__ void cpa16(uint32_t dst, const void* src) {
    asm volatile("cp.async.cg.shared.global [%0], [%1], 16;" :: "r"(dst), "l"(src));
}
#define CPA_COMMIT() asm volatile("cp.async.commit_group;" ::: "memory")
#define CPA_WAIT1()  asm volatile("cp.async.wait_group 1;" ::: "memory")
#define CPA_WAIT0()  asm volatile("cp.async.wait_group 0;" ::: "memory")

extern __shared__ __align__(16) float smemf[];

// ============================================================================
// Whh -> tf32 hi/lo fp32 planes (once per launch)
// ============================================================================
__global__ void conv_whh_kernel(const float* __restrict__ Whh) {
    size_t i = (size_t)blockIdx.x * 256 + threadIdx.x;
    unsigned hi, lo;
    split_tf32(Whh[i], hi, lo);
    g_whh_pl[0][i] = __uint_as_float(hi);
    g_whh_pl[1][i] = __uint_as_float(lo);
}

// ============================================================================
// Generic 3xTF32 GEMM: C[M,N] = A[M,K] * B[N,K]^T + bias[N]  (proven)
// ============================================================================
#define GPITF 68
#define GEMM_SMEM ((128 + 64) * GPITF * 4)   // 52224 bytes

__launch_bounds__(256)
__global__ void gemm_tf32(const float* __restrict__ A,
                          const float* __restrict__ Bm,
                          const float* __restrict__ bias,
                          float* __restrict__ C,
                          int M, int N, int K) {
    float* As = smemf;                 // [128][GPITF]
    float* Bs = smemf + 128 * GPITF;   // [64][GPITF]

    const int tid    = threadIdx.x;
    const int lane   = tid & 31;
    const int wid    = tid >> 5;
    const int warp_m = wid >> 1;
    const int warp_n = wid & 1;
    const int row0   = blockIdx.y * 128;
    const int col0   = blockIdx.x * 64;

    float acc[2][4][4];
#pragma unroll
    for (int i = 0; i < 2; i++)
#pragma unroll
        for (int j = 0; j < 4; j++)
#pragma unroll
            for (int k = 0; k < 4; k++) acc[i][j][k] = 0.0f;

    for (int k0 = 0; k0 < K; k0 += 64) {
#pragma unroll
        for (int i = 0; i < 8; i++) {
            int idx = tid + i * 256;
            int r = idx >> 4, q = idx & 15;
            *(float4*)&As[r * GPITF + q * 4] =
                *(const float4*)(A + (size_t)(row0 + r) * K + k0 + q * 4);
        }
#pragma unroll
        for (int i = 0; i < 4; i++) {
            int idx = tid + i * 256;
            int r = idx >> 4, q = idx & 15;
            *(float4*)&Bs[r * GPITF + q * 4] =
                *(const float4*)(Bm + (size_t)(col0 + r) * K + k0 + q * 4);
        }
        __syncthreads();

#pragma unroll
        for (int kk = 0; kk < 64; kk += 8) {
            unsigned ahi[2][4], alo[2][4];
#pragma unroll
            for (int mt = 0; mt < 2; mt++) {
                int row = warp_m * 32 + mt * 16 + (lane >> 2);
                int c0  = kk + (lane & 3);
                split_tf32(As[row * GPITF + c0],           ahi[mt][0], alo[mt][0]);
                split_tf32(As[(row + 8) * GPITF + c0],     ahi[mt][1], alo[mt][1]);
                split_tf32(As[row * GPITF + c0 + 4],       ahi[mt][2], alo[mt][2]);
                split_tf32(As[(row + 8) * GPITF + c0 + 4], ahi[mt][3], alo[mt][3]);
            }
            unsigned bhi[4][2], blo[4][2];
#pragma unroll
            for (int nt = 0; nt < 4; nt++) {
                int brow = warp_n * 32 + nt * 8 + (lane >> 2);
                int bc   = kk + (lane & 3);
                split_tf32(Bs[brow * GPITF + bc],     bhi[nt][0], blo[nt][0]);
                split_tf32(Bs[brow * GPITF + bc + 4], bhi[nt][1], blo[nt][1]);
            }
#pragma unroll
            for (int mt = 0; mt < 2; mt++)
#pragma unroll
                for (int nt = 0; nt < 4; nt++) {
                    mma_tf32(acc[mt][nt], ahi[mt], bhi[nt]);
                    mma_tf32(acc[mt][nt], ahi[mt], blo[nt]);
                    mma_tf32(acc[mt][nt], alo[mt], bhi[nt]);
                }
        }
        __syncthreads();
    }

#pragma unroll
    for (int mt = 0; mt < 2; mt++)
#pragma unroll
        for (int nt = 0; nt < 4; nt++) {
            int row = row0 + warp_m * 32 + mt * 16 + (lane >> 2);
            int col = col0 + warp_n * 32 + nt * 8 + (lane & 3) * 2;
            float b0 = bias[col], b1 = bias[col + 1];
            *(float2*)(C + (size_t)row * N + col) =
                make_float2(acc[mt][nt][0] + b0, acc[mt][nt][1] + b1);
            *(float2*)(C + (size_t)(row + 8) * N + col) =
                make_float2(acc[mt][nt][2] + b0, acc[mt][nt][3] + b1);
        }
}

// ============================================================================
// LSTM step via 3xTF32. Pre-split hi/lo planes live in GLOBAL (written by the
// previous step's epilogue / conv kernel); loader is pure cp.async into a
// 2-stage smem pipeline — zero split ALU, zero register round-trip.
// 512 threads = 16 warps: 4 warp_m x 4-way K-split. Warp tile 32m x 32n.
// Grid: 128 CTAs; CTA = 128 batch rows x 32 packed gate-cols.
// Packed col l (0..31): j = bx*8 + l/4, gate g = l%4 (R7-validated mapping).
// ============================================================================
#define KCS   64
#define PITF  68                      // plane pitch (floats), conflict-free
#define A_PL  (128 * PITF)            // one A plane: 8704 floats
#define B_PL  (32 * PITF)             // one B plane: 2176 floats
#define STG_F (2 * A_PL + 2 * B_PL)   // floats per stage: 21760
#define STEP_SMEM (2 * STG_F * 4)     // 174080 bytes
#define GSM_P (128 * 34)              // one staging partial: 4352 floats

__launch_bounds__(512)
__global__ void lstm_step_tf32(int t, const float* __restrict__ bhh) {
    const int tid    = threadIdx.x;
    const int lane   = tid & 31;
    const int wid    = tid >> 5;
    const int warp_m = wid >> 2;      // 0..3: m base warp_m*32
    const int ks     = wid & 3;       // 0..3: K-split slice
    const int bx     = blockIdx.x;

    float* gsm = smemf;               // [4][128][34] partials, reuses stage 0

    float acc[2][4][4];               // [mt][nt][4]
#pragma unroll
    for (int i = 0; i < 2; i++)
#pragma unroll
        for (int j = 0; j < 4; j++)
#pragma unroll
            for (int k = 0; k < 4; k++) acc[i][j][k] = 0.0f;

    if (t > 0) {
        const float* hp_hi = g_h_pl[0][t & 1];
        const float* hp_lo = g_h_pl[1][t & 1];

        // loader thread mapping (fixed per thread)
        const int ar = tid >> 2;              // A row 0..127
        const int aq = tid & 3;               // float4 idx 0..3 (of 16) base
        const int br = tid >> 4;              // packed l 0..31
        const int bq = tid & 15;              // float4 idx 0..15
        const int b_nglob = (br & 3) * HID + bx * 8 + (br >> 2);

        // issue chunk c into stage s (pure cp.async)
        auto issue_chunk = [&](int c, int s) {
            float* Ahi = smemf + s * STG_F;
            float* Alo = Ahi + A_PL;
            float* Bhi = Alo + A_PL;
            float* Blo = Bhi + B_PL;
            const int kc = c * KCS;
            // A: 128 rows x 64 floats per plane = 2048 float4; 512 thr -> 4 each
#pragma unroll
            for (int i = 0; i < 4; i++) {
                int q = aq + i * 4;
                cpa16(smaddr_(&Ahi[ar * PITF + q * 4]),
                      hp_hi + (size_t)ar * HID + kc + q * 4);
                cpa16(smaddr_(&Alo[ar * PITF + q * 4]),
                      hp_lo + (size_t)ar * HID + kc + q * 4);
            }
            // B: 32 rows x 64 floats per plane = 512 float4; 512 thr -> 1 each
            cpa16(smaddr_(&Bhi[br * PITF + bq * 4]),
                  g_whh_pl[0] + (size_t)b_nglob * HID + kc + bq * 4);
            cpa16(smaddr_(&Blo[br * PITF + bq * 4]),
                  g_whh_pl[1] + (size_t)b_nglob * HID + kc + bq * 4);
        };

        issue_chunk(0, 0);
        CPA_COMMIT();

        for (int c = 0; c < HID / KCS; c++) {
            float* Ahi = smemf + (c & 1) * STG_F;
            float* Alo = Ahi + A_PL;
            float* Bhi = Alo + A_PL;
            float* Blo = Bhi + B_PL;

            if (c + 1 < HID / KCS) {
                issue_chunk(c + 1, (c + 1) & 1);
                CPA_COMMIT();
                CPA_WAIT1();
            } else {
                CPA_WAIT0();
            }
            __syncthreads();

            // ---- mainloop: pure LDS + MMA; this warp's 2 kk-steps ----
#pragma unroll
            for (int kk2 = 0; kk2 < 2; kk2++) {
                const int kk = (ks * 2 + kk2) * 8;
                unsigned ahi[2][4], alo[2][4], bhi[4][2], blo[4][2];
#pragma unroll
                for (int mt = 0; mt < 2; mt++) {
                    int row = warp_m * 32 + mt * 16 + (lane >> 2);
                    int c0  = kk + (lane & 3);
                    ahi[mt][0] = *(unsigned*)&Ahi[row * PITF + c0];
                    ahi[mt][1] = *(unsigned*)&Ahi[(row + 8) * PITF + c0];
                    ahi[mt][2] = *(unsigned*)&Ahi[row * PITF + c0 + 4];
                    ahi[mt][3] = *(unsigned*)&Ahi[(row + 8) * PITF + c0 + 4];
                    alo[mt][0] = *(unsigned*)&Alo[row * PITF + c0];
                    alo[mt][1] = *(unsigned*)&Alo[(row + 8) * PITF + c0];
                    alo[mt][2] = *(unsigned*)&Alo[row * PITF + c0 + 4];
                    alo[mt][3] = *(unsigned*)&Alo[(row + 8) * PITF + c0 + 4];
                }
#pragma unroll
                for (int nt = 0; nt < 4; nt++) {
                    int brow = nt * 8 + (lane >> 2);
                    int bc   = kk + (lane & 3);
                    bhi[nt][0] = *(unsigned*)&Bhi[brow * PITF + bc];
                    bhi[nt][1] = *(unsigned*)&Bhi[brow * PITF + bc + 4];
                    blo[nt][0] = *(unsigned*)&Blo[brow * PITF + bc];
                    blo[nt][1] = *(unsigned*)&Blo[brow * PITF + bc + 4];
                }
#pragma unroll
                for (int mt = 0; mt < 2; mt++)
#pragma unroll
                    for (int nt = 0; nt < 4; nt++) {
                        mma_tf32(acc[mt][nt], ahi[mt], bhi[nt]);
                        mma_tf32(acc[mt][nt], ahi[mt], blo[nt]);
                        mma_tf32(acc[mt][nt], alo[mt], bhi[nt]);
                    }
            }
            __syncthreads();
        }
    }

    // stage K-partial gate pre-activations: gsm[ks][b][l], pitch 34
#pragma unroll
    for (int mt = 0; mt < 2; mt++)
#pragma unroll
        for (int nt = 0; nt < 4; nt++) {
            int row = warp_m * 32 + mt * 16 + (lane >> 2);
            int col = nt * 8 + (lane & 3) * 2;
            *(float2*)(gsm + ks * GSM_P + row * 34 + col) =
                make_float2(acc[mt][nt][0], acc[mt][nt][1]);
            *(float2*)(gsm + ks * GSM_P + (row + 8) * 34 + col) =
                make_float2(acc[mt][nt][2], acc[mt][nt][3]);
        }
    __syncthreads();

    // fused activation epilogue: 1024 (b, jj) items / 512 threads.
    // Splits h into tf32 hi/lo planes HERE (once per element, for next step).
    const float* xp   = g_xproj + (size_t)t * BATCH * G4;
    const float* cin  = g_c[t & 1];
    float*       cout = g_c[(t + 1) & 1];
    float*       hout = g_hs + (size_t)t * BATCH * HID;
    float*       ph   = g_h_pl[0][(t + 1) & 1];
    float*       pl   = g_h_pl[1][(t + 1) & 1];

#pragma unroll
    for (int it = 0; it < 2; it++) {
        int item = tid + it * 512;
        int b    = item & 127;
        int jj   = item >> 7;           // 0..7
        int j    = bx * 8 + jj;
        int base = b * 34 + jj * 4;
        float g0 = 0.f, g1 = 0.f, g2 = 0.f, g3 = 0.f;
#pragma unroll
        for (int p = 0; p < 4; p++) {
            g0 += gsm[p * GSM_P + base + 0];
            g1 += gsm[p * GSM_P + base + 1];
            g2 += gsm[p * GSM_P + base + 2];
            g3 += gsm[p * GSM_P + base + 3];
        }
        size_t xb = (size_t)b * G4 + j;
        float gi = g0 + xp[xb]           + bhh[j];
        float gf = g1 + xp[xb + HID]     + bhh[HID + j];
        float gg = g2 + xp[xb + 2 * HID] + bhh[2 * HID + j];
        float go = g3 + xp[xb + 3 * HID] + bhh[3 * HID + j];
        float cold = (t > 0) ? cin[b * HID + j] : 0.0f;
        float cn = sigmoidf_(gf) * cold + sigmoidf_(gi) * tanhf(gg);
        float hn = sigmoidf_(go) * tanhf(cn);
        cout[b * HID + j] = cn;
        hout[(size_t)b * HID + j] = hn;
        unsigned hi, lo;
        split_tf32(hn, hi, lo);
        ph[b * HID + j] = __uint_as_float(hi);
        pl[b * HID + j] = __uint_as_float(lo);
    }
}

// ============================================================================
// In-place row-wise log_softmax over 256 columns. One block per row.
// ============================================================================
__launch_bounds__(256)
__global__ void logsoftmax_kernel(float* __restrict__ out) {
    __shared__ float red[256];
    const size_t r = blockIdx.x;
    const int tid  = threadIdx.x;
    float v = out[r * 256 + tid];

    red[tid] = v;
    __syncthreads();
#pragma unroll
    for (int s = 128; s > 0; s >>= 1) {
        if (tid < s) red[tid] = fmaxf(red[tid], red[tid + s]);
        __syncthreads();
    }
    float m = red[0];
    __syncthreads();

    float e = expf(v - m);
    red[tid] = e;
    __syncthreads();
#pragma unroll
    for (int s = 128; s > 0; s >>= 1) {
        if (tid < s) red[tid] += red[tid + s];
        __syncthreads();
    }
    float lse = logf(red[0]) + m;
    out[r * 256 + tid] = v - lse;
}

// ============================================================================
extern "C" void kernel_launch(void* const* d_in, const int* in_sizes, int n_in,
                              void* d_out, int out_size) {
    const float* inp  = (const float*)d_in[0];  // [512,128,256]
    const float* Wxh  = (const float*)d_in[1];  // [4096,256]
    const float* bxh  = (const float*)d_in[2];  // [4096]
    const float* Whh  = (const float*)d_in[3];  // [4096,1024]
    const float* bhh  = (const float*)d_in[4];  // [4096]
    const float* Wout = (const float*)d_in[5];  // [256,1024]
    const float* bout = (const float*)d_in[6];  // [256]
    float* out = (float*)d_out;                 // [512,128,256] fp32

    float* xproj; cudaGetSymbolAddress((void**)&xproj, g_xproj);
    float* hs;    cudaGetSymbolAddress((void**)&hs, g_hs);

    cudaFuncSetAttribute(lstm_step_tf32,
                         cudaFuncAttributeMaxDynamicSharedMemorySize, STEP_SMEM);
    cudaFuncSetAttribute(gemm_tf32,
                         cudaFuncAttributeMaxDynamicSharedMemorySize, GEMM_SMEM);

    // 0) split Whh into tf32 hi/lo planes (constant across steps)
    conv_whh_kernel<<<(G4 * HID) / 256, 256>>>(Whh);

    // 1) x_proj[T*B, 4H] = inp @ Wxh^T + bxh  (3xTF32)
    gemm_tf32<<<dim3(G4 / 64, TB / 128), 256, GEMM_SMEM>>>(
        inp, Wxh, bxh, xproj, TB, G4, INPD);

    // 2) recurrence (3xTF32, global pre-split planes + cp.async pipeline)
    for (int t = 0; t < SEQ; t++)
        lstm_step_tf32<<<128, 512, STEP_SMEM>>>(t, bhh);

    // 3) out[T*B, 256] = hs @ Wout^T + bout  (3xTF32)
    gemm_tf32<<<dim3(INPD / 64, TB / 128), 256, GEMM_SMEM>>>(
        hs, Wout, bout, out, TB, INPD, HID);

    // 4) log_softmax rows
    logsoftmax_kernel<<<TB, 256>>>(out);
}

// round 12
// speedup vs baseline: 1.2412x; 1.2412x over previous
#include <cuda_runtime.h>
#include <math.h>
#include <stdint.h>

#define SEQ   512
#define BATCH 128
#define INPD  256
#define HID   1024
#define G4    4096
#define TB    (SEQ*BATCH)   // 65536 rows

// ---- scratch (allocation-free: device globals) ----
__device__ float g_xproj[(size_t)TB * G4];   // 1 GiB: [T*B, 4H]
__device__ float g_hs[(size_t)TB * HID];     // 256 MiB: h per timestep (fp32)
__device__ float g_c[2][BATCH * HID];        // ping-pong cell state

__device__ __forceinline__ float sigmoidf_(float x) { return 1.0f / (1.0f + expf(-x)); }

// ============================================================================
// tf32 mma helpers (m16n8k8, 3xTF32 fp32-emulation)
// ============================================================================
__device__ __forceinline__ unsigned cvt_tf32(float x) {
    unsigned r;
    asm("cvt.rna.tf32.f32 %0, %1;" : "=r"(r) : "f"(x));
    return r;
}
__device__ __forceinline__ void split_tf32(float x, unsigned& hi, unsigned& lo) {
    hi = cvt_tf32(x);
    lo = cvt_tf32(x - __uint_as_float(hi));
}
__device__ __forceinline__ void mma_tf32(float* c, const unsigned* a, const unsigned* b) {
    asm volatile("mma.sync.aligned.m16n8k8.row.col.f32.tf32.tf32.f32 "
        "{%0,%1,%2,%3},{%4,%5,%6,%7},{%8,%9},{%0,%1,%2,%3};"
        : "+f"(c[0]), "+f"(c[1]), "+f"(c[2]), "+f"(c[3])
        : "r"(a[0]), "r"(a[1]), "r"(a[2]), "r"(a[3]), "r"(b[0]), "r"(b[1]));
}

extern __shared__ __align__(16) float smemf[];

// ============================================================================
// Generic 3xTF32 GEMM: C[M,N] = A[M,K] * B[N,K]^T + bias[N]  (proven)
// ============================================================================
#define GPITF 68
#define GEMM_SMEM ((128 + 64) * GPITF * 4)   // 52224 bytes

__launch_bounds__(256)
__global__ void gemm_tf32(const float* __restrict__ A,
                          const float* __restrict__ Bm,
                          const float* __restrict__ bias,
                          float* __restrict__ C,
                          int M, int N, int K) {
    float* As = smemf;                 // [128][GPITF]
    float* Bs = smemf + 128 * GPITF;   // [64][GPITF]

    const int tid    = threadIdx.x;
    const int lane   = tid & 31;
    const int wid    = tid >> 5;
    const int warp_m = wid >> 1;
    const int warp_n = wid & 1;
    const int row0   = blockIdx.y * 128;
    const int col0   = blockIdx.x * 64;

    float acc[2][4][4];
#pragma unroll
    for (int i = 0; i < 2; i++)
#pragma unroll
        for (int j = 0; j < 4; j++)
#pragma unroll
            for (int k = 0; k < 4; k++) acc[i][j][k] = 0.0f;

    for (int k0 = 0; k0 < K; k0 += 64) {
#pragma unroll
        for (int i = 0; i < 8; i++) {
            int idx = tid + i * 256;
            int r = idx >> 4, q = idx & 15;
            *(float4*)&As[r * GPITF + q * 4] =
                *(const float4*)(A + (size_t)(row0 + r) * K + k0 + q * 4);
        }
#pragma unroll
        for (int i = 0; i < 4; i++) {
            int idx = tid + i * 256;
            int r = idx >> 4, q = idx & 15;
            *(float4*)&Bs[r * GPITF + q * 4] =
                *(const float4*)(Bm + (size_t)(col0 + r) * K + k0 + q * 4);
        }
        __syncthreads();

#pragma unroll
        for (int kk = 0; kk < 64; kk += 8) {
            unsigned ahi[2][4], alo[2][4];
#pragma unroll
            for (int mt = 0; mt < 2; mt++) {
                int row = warp_m * 32 + mt * 16 + (lane >> 2);
                int c0  = kk + (lane & 3);
                split_tf32(As[row * GPITF + c0],           ahi[mt][0], alo[mt][0]);
                split_tf32(As[(row + 8) * GPITF + c0],     ahi[mt][1], alo[mt][1]);
                split_tf32(As[row * GPITF + c0 + 4],       ahi[mt][2], alo[mt][2]);
                split_tf32(As[(row + 8) * GPITF + c0 + 4], ahi[mt][3], alo[mt][3]);
            }
            unsigned bhi[4][2], blo[4][2];
#pragma unroll
            for (int nt = 0; nt < 4; nt++) {
                int brow = warp_n * 32 + nt * 8 + (lane >> 2);
                int bc   = kk + (lane & 3);
                split_tf32(Bs[brow * GPITF + bc],     bhi[nt][0], blo[nt][0]);
                split_tf32(Bs[brow * GPITF + bc + 4], bhi[nt][1], blo[nt][1]);
            }
#pragma unroll
            for (int mt = 0; mt < 2; mt++)
#pragma unroll
                for (int nt = 0; nt < 4; nt++) {
                    mma_tf32(acc[mt][nt], ahi[mt], bhi[nt]);
                    mma_tf32(acc[mt][nt], ahi[mt], blo[nt]);
                    mma_tf32(acc[mt][nt], alo[mt], bhi[nt]);
                }
        }
        __syncthreads();
    }

#pragma unroll
    for (int mt = 0; mt < 2; mt++)
#pragma unroll
        for (int nt = 0; nt < 4; nt++) {
            int row = row0 + warp_m * 32 + mt * 16 + (lane >> 2);
            int col = col0 + warp_n * 32 + nt * 8 + (lane & 3) * 2;
            float b0 = bias[col], b1 = bias[col + 1];
            *(float2*)(C + (size_t)row * N + col) =
                make_float2(acc[mt][nt][0] + b0, acc[mt][nt][1] + b1);
            *(float2*)(C + (size_t)(row + 8) * N + col) =
                make_float2(acc[mt][nt][2] + b0, acc[mt][nt][3] + b1);
        }
}

// ============================================================================
// LSTM step via 3xTF32, R10 structure at HALF-M per CTA for 2 CTAs/SM:
// Grid: 256 CTAs = 128 N-tiles (32 packed gate-cols) x 2 M-halves (64 rows).
// 256 threads = 8 warps: 2 warp_m x 4-way K-split; warp tile 32m x 32n.
// In-register tf32 split at staging (R10-proven), register-prefetch pipeline.
// Packed col l (0..31): j = ntile*8 + l/4, gate g = l%4 (R7-validated).
// ============================================================================
#define KCS   64
#define PITF  68                      // plane pitch (floats), conflict-free
#define A_PL  (64 * PITF)             // one A plane: 4352 floats
#define B_PL  (32 * PITF)             // one B plane: 2176 floats
#define STEP_SMEM ((2 * A_PL + 2 * B_PL) * 4)   // 52224 bytes -> 2 CTAs/SM
#define GSM_P (64 * 34)               // one staging partial: 2176 floats

__launch_bounds__(256, 2)
__global__ void lstm_step_tf32(int t,
                               const float* __restrict__ Whh,
                               const float* __restrict__ bhh) {
    const int tid    = threadIdx.x;
    const int lane   = tid & 31;
    const int wid    = tid >> 5;
    const int warp_m = wid >> 2;      // 0..1: m base warp_m*32
    const int ks     = wid & 3;       // 0..3: K-split slice
    const int ntile  = blockIdx.x >> 1;   // 0..127: N-tile
    const int mh     = blockIdx.x & 1;    // 0..1: M-half (rows mh*64..+64)

    float* Ahi = smemf;
    float* Alo = Ahi + A_PL;
    float* Bhi = Alo + A_PL;
    float* Blo = Bhi + B_PL;
    float* gsm = smemf;               // [4][64][34] partials, reuses planes

    float acc[2][4][4];               // [mt][nt][4]
#pragma unroll
    for (int i = 0; i < 2; i++)
#pragma unroll
        for (int j = 0; j < 4; j++)
#pragma unroll
            for (int k = 0; k < 4; k++) acc[i][j][k] = 0.0f;

    if (t > 0) {
        const float* hprev = g_hs + (size_t)(t - 1) * BATCH * HID + (size_t)mh * 64 * HID;

        // per-thread prefetch registers (chunk granularity)
        float4 rA[4];   // A: 64 rows x 16 float4 = 1024 / 256 thr = 4 each
        float4 rB[2];   // B: 32 rows x 16 float4 = 512 / 256 thr = 2 each
        const int arr[4] = { tid >> 4, (tid + 256) >> 4,
                             (tid + 512) >> 4, (tid + 768) >> 4 };
        const int aq = tid & 15;
        const int brr[2] = { tid >> 4, (tid + 256) >> 4 };
        const int bq = tid & 15;
        int bng[2];
#pragma unroll
        for (int i = 0; i < 2; i++)
            bng[i] = (brr[i] & 3) * HID + ntile * 8 + (brr[i] >> 2);

        // prologue: LDG chunk 0
#pragma unroll
        for (int i = 0; i < 4; i++)
            rA[i] = *(const float4*)(hprev + (size_t)arr[i] * HID + aq * 4);
#pragma unroll
        for (int i = 0; i < 2; i++)
            rB[i] = *(const float4*)(Whh + (size_t)bng[i] * HID + bq * 4);

        for (int c = 0; c < HID / KCS; c++) {
            // ---- split current chunk regs into hi/lo planes ----
#pragma unroll
            for (int i = 0; i < 4; i++) {
                const float v[4] = { rA[i].x, rA[i].y, rA[i].z, rA[i].w };
                unsigned h4[4], l4[4];
#pragma unroll
                for (int e = 0; e < 4; e++) split_tf32(v[e], h4[e], l4[e]);
                *(uint4*)&Ahi[arr[i] * PITF + aq * 4] = make_uint4(h4[0], h4[1], h4[2], h4[3]);
                *(uint4*)&Alo[arr[i] * PITF + aq * 4] = make_uint4(l4[0], l4[1], l4[2], l4[3]);
            }
#pragma unroll
            for (int i = 0; i < 2; i++) {
                const float v[4] = { rB[i].x, rB[i].y, rB[i].z, rB[i].w };
                unsigned h4[4], l4[4];
#pragma unroll
                for (int e = 0; e < 4; e++) split_tf32(v[e], h4[e], l4[e]);
                *(uint4*)&Bhi[brr[i] * PITF + bq * 4] = make_uint4(h4[0], h4[1], h4[2], h4[3]);
                *(uint4*)&Blo[brr[i] * PITF + bq * 4] = make_uint4(l4[0], l4[1], l4[2], l4[3]);
            }
            __syncthreads();

            // ---- issue LDG for next chunk (latency hidden by compute) ----
            if (c + 1 < HID / KCS) {
                const int kc = (c + 1) * KCS;
#pragma unroll
                for (int i = 0; i < 4; i++)
                    rA[i] = *(const float4*)(hprev + (size_t)arr[i] * HID + kc + aq * 4);
#pragma unroll
                for (int i = 0; i < 2; i++)
                    rB[i] = *(const float4*)(Whh + (size_t)bng[i] * HID + kc + bq * 4);
            }

            // ---- mainloop: pure LDS + MMA; this warp's 2 kk-steps ----
#pragma unroll
            for (int kk2 = 0; kk2 < 2; kk2++) {
                const int kk = (ks * 2 + kk2) * 8;
                unsigned ahi[2][4], alo[2][4], bhi[4][2], blo[4][2];
#pragma unroll
                for (int mt = 0; mt < 2; mt++) {
                    int row = warp_m * 32 + mt * 16 + (lane >> 2);
                    int c0  = kk + (lane & 3);
                    ahi[mt][0] = *(unsigned*)&Ahi[row * PITF + c0];
                    ahi[mt][1] = *(unsigned*)&Ahi[(row + 8) * PITF + c0];
                    ahi[mt][2] = *(unsigned*)&Ahi[row * PITF + c0 + 4];
                    ahi[mt][3] = *(unsigned*)&Ahi[(row + 8) * PITF + c0 + 4];
                    alo[mt][0] = *(unsigned*)&Alo[row * PITF + c0];
                    alo[mt][1] = *(unsigned*)&Alo[(row + 8) * PITF + c0];
                    alo[mt][2] = *(unsigned*)&Alo[row * PITF + c0 + 4];
                    alo[mt][3] = *(unsigned*)&Alo[(row + 8) * PITF + c0 + 4];
                }
#pragma unroll
                for (int nt = 0; nt < 4; nt++) {
                    int brow = nt * 8 + (lane >> 2);
                    int bc   = kk + (lane & 3);
                    bhi[nt][0] = *(unsigned*)&Bhi[brow * PITF + bc];
                    bhi[nt][1] = *(unsigned*)&Bhi[brow * PITF + bc + 4];
                    blo[nt][0] = *(unsigned*)&Blo[brow * PITF + bc];
                    blo[nt][1] = *(unsigned*)&Blo[brow * PITF + bc + 4];
                }
#pragma unroll
                for (int mt = 0; mt < 2; mt++)
#pragma unroll
                    for (int nt = 0; nt < 4; nt++) {
                        mma_tf32(acc[mt][nt], ahi[mt], bhi[nt]);
                        mma_tf32(acc[mt][nt], ahi[mt], blo[nt]);
                        mma_tf32(acc[mt][nt], alo[mt], bhi[nt]);
                    }
            }
            __syncthreads();
        }
    }

    // stage K-partial gate pre-activations: gsm[ks][b_loc][l], pitch 34
#pragma unroll
    for (int mt = 0; mt < 2; mt++)
#pragma unroll
        for (int nt = 0; nt < 4; nt++) {
            int row = warp_m * 32 + mt * 16 + (lane >> 2);
            int col = nt * 8 + (lane & 3) * 2;
            *(float2*)(gsm + ks * GSM_P + row * 34 + col) =
                make_float2(acc[mt][nt][0], acc[mt][nt][1]);
            *(float2*)(gsm + ks * GSM_P + (row + 8) * 34 + col) =
                make_float2(acc[mt][nt][2], acc[mt][nt][3]);
        }
    __syncthreads();

    // fused activation epilogue: 512 (b_loc, jj) items / 256 threads
    const float* xp   = g_xproj + (size_t)t * BATCH * G4;
    const float* cin  = g_c[t & 1];
    float*       cout = g_c[(t + 1) & 1];
    float*       hout = g_hs + (size_t)t * BATCH * HID;

#pragma unroll
    for (int it = 0; it < 2; it++) {
        int item  = tid + it * 256;
        int b_loc = item & 63;
        int jj    = item >> 6;          // 0..7
        int b     = mh * 64 + b_loc;
        int j     = ntile * 8 + jj;
        int base  = b_loc * 34 + jj * 4;
        float g0 = 0.f, g1 = 0.f, g2 = 0.f, g3 = 0.f;
#pragma unroll
        for (int p = 0; p < 4; p++) {
            g0 += gsm[p * GSM_P + base + 0];
            g1 += gsm[p * GSM_P + base + 1];
            g2 += gsm[p * GSM_P + base + 2];
            g3 += gsm[p * GSM_P + base + 3];
        }
        size_t xb = (size_t)b * G4 + j;
        float gi = g0 + xp[xb]           + bhh[j];
        float gf = g1 + xp[xb + HID]     + bhh[HID + j];
        float gg = g2 + xp[xb + 2 * HID] + bhh[2 * HID + j];
        float go = g3 + xp[xb + 3 * HID] + bhh[3 * HID + j];
        float cold = (t > 0) ? cin[b * HID + j] : 0.0f;
        float cn = sigmoidf_(gf) * cold + sigmoidf_(gi) * tanhf(gg);
        float hn = sigmoidf_(go) * tanhf(cn);
        cout[b * HID + j] = cn;
        hout[(size_t)b * HID + j] = hn;
    }
}

// ============================================================================
// In-place row-wise log_softmax over 256 columns. One block per row.
// ============================================================================
__launch_bounds__(256)
__global__ void logsoftmax_kernel(float* __restrict__ out) {
    __shared__ float red[256];
    const size_t r = blockIdx.x;
    const int tid  = threadIdx.x;
    float v = out[r * 256 + tid];

    red[tid] = v;
    __syncthreads();
#pragma unroll
    for (int s = 128; s > 0; s >>= 1) {
        if (tid < s) red[tid] = fmaxf(red[tid], red[tid + s]);
        __syncthreads();
    }
    float m = red[0];
    __syncthreads();

    float e = expf(v - m);
    red[tid] = e;
    __syncthreads();
#pragma unroll
    for (int s = 128; s > 0; s >>= 1) {
        if (tid < s) red[tid] += red[tid + s];
        __syncthreads();
    }
    float lse = logf(red[0]) + m;
    out[r * 256 + tid] = v - lse;
}

// ============================================================================
extern "C" void kernel_launch(void* const* d_in, const int* in_sizes, int n_in,
                              void* d_out, int out_size) {
    const float* inp  = (const float*)d_in[0];  // [512,128,256]
    const float* Wxh  = (const float*)d_in[1];  // [4096,256]
    const float* bxh  = (const float*)d_in[2];  // [4096]
    const float* Whh  = (const float*)d_in[3];  // [4096,1024]
    const float* bhh  = (const float*)d_in[4];  // [4096]
    const float* Wout = (const float*)d_in[5];  // [256,1024]
    const float* bout = (const float*)d_in[6];  // [256]
    float* out = (float*)d_out;                 // [512,128,256] fp32

    float* xproj; cudaGetSymbolAddress((void**)&xproj, g_xproj);
    float* hs;    cudaGetSymbolAddress((void**)&hs, g_hs);

    cudaFuncSetAttribute(lstm_step_tf32,
                         cudaFuncAttributeMaxDynamicSharedMemorySize, STEP_SMEM);
    cudaFuncSetAttribute(gemm_tf32,
                         cudaFuncAttributeMaxDynamicSharedMemorySize, GEMM_SMEM);

    // 1) x_proj[T*B, 4H] = inp @ Wxh^T + bxh  (3xTF32)
    gemm_tf32<<<dim3(G4 / 64, TB / 128), 256, GEMM_SMEM>>>(
        inp, Wxh, bxh, xproj, TB, G4, INPD);

    // 2) recurrence (3xTF32, half-M CTAs, 2 CTAs/SM for stall overlap)
    for (int t = 0; t < SEQ; t++)
        lstm_step_tf32<<<256, 256, STEP_SMEM>>>(t, Whh, bhh);

    // 3) out[T*B, 256] = hs @ Wout^T + bout  (3xTF32)
    gemm_tf32<<<dim3(INPD / 64, TB / 128), 256, GEMM_SMEM>>>(
        hs, Wout, bout, out, TB, INPD, HID);

    // 4) log_softmax rows
    logsoftmax_kernel<<<TB, 256>>>(out);
}

// round 13
// speedup vs baseline: 1.5403x; 1.2411x over previous
#include <cuda_runtime.h>
#include <math.h>
#include <stdint.h>

#define SEQ   512
#define BATCH 128
#define INPD  256
#define HID   1024
#define G4    4096
#define TB    (SEQ*BATCH)   // 65536 rows

// ---- scratch (allocation-free: device globals) ----
__device__ float g_xproj[(size_t)TB * G4];   // 1 GiB: [T*B, 4H]
__device__ float g_hs[(size_t)TB * HID];     // 256 MiB: h per timestep (fp32)
__device__ float g_c[2][BATCH * HID];        // ping-pong cell state

__device__ __forceinline__ float sigmoidf_(float x) { return 1.0f / (1.0f + expf(-x)); }

// ============================================================================
// tf32 mma helpers (m16n8k8, split-tf32 fp32-emulation)
// ============================================================================
__device__ __forceinline__ unsigned cvt_tf32(float x) {
    unsigned r;
    asm("cvt.rna.tf32.f32 %0, %1;" : "=r"(r) : "f"(x));
    return r;
}
__device__ __forceinline__ void split_tf32(float x, unsigned& hi, unsigned& lo) {
    hi = cvt_tf32(x);
    lo = cvt_tf32(x - __uint_as_float(hi));
}
__device__ __forceinline__ void mma_tf32(float* c, const unsigned* a, const unsigned* b) {
    asm volatile("mma.sync.aligned.m16n8k8.row.col.f32.tf32.tf32.f32 "
        "{%0,%1,%2,%3},{%4,%5,%6,%7},{%8,%9},{%0,%1,%2,%3};"
        : "+f"(c[0]), "+f"(c[1]), "+f"(c[2]), "+f"(c[3])
        : "r"(a[0]), "r"(a[1]), "r"(a[2]), "r"(a[3]), "r"(b[0]), "r"(b[1]));
}

extern __shared__ __align__(16) float smemf[];

// ============================================================================
// Generic 3xTF32 GEMM: C[M,N] = A[M,K] * B[N,K]^T + bias[N]  (proven; keeps
// 3 products for extra margin — not the bottleneck)
// ============================================================================
#define GPITF 68
#define GEMM_SMEM ((128 + 64) * GPITF * 4)   // 52224 bytes

__launch_bounds__(256)
__global__ void gemm_tf32(const float* __restrict__ A,
                          const float* __restrict__ Bm,
                          const float* __restrict__ bias,
                          float* __restrict__ C,
                          int M, int N, int K) {
    float* As = smemf;                 // [128][GPITF]
    float* Bs = smemf + 128 * GPITF;   // [64][GPITF]

    const int tid    = threadIdx.x;
    const int lane   = tid & 31;
    const int wid    = tid >> 5;
    const int warp_m = wid >> 1;
    const int warp_n = wid & 1;
    const int row0   = blockIdx.y * 128;
    const int col0   = blockIdx.x * 64;

    float acc[2][4][4];
#pragma unroll
    for (int i = 0; i < 2; i++)
#pragma unroll
        for (int j = 0; j < 4; j++)
#pragma unroll
            for (int k = 0; k < 4; k++) acc[i][j][k] = 0.0f;

    for (int k0 = 0; k0 < K; k0 += 64) {
#pragma unroll
        for (int i = 0; i < 8; i++) {
            int idx = tid + i * 256;
            int r = idx >> 4, q = idx & 15;
            *(float4*)&As[r * GPITF + q * 4] =
                *(const float4*)(A + (size_t)(row0 + r) * K + k0 + q * 4);
        }
#pragma unroll
        for (int i = 0; i < 4; i++) {
            int idx = tid + i * 256;
            int r = idx >> 4, q = idx & 15;
            *(float4*)&Bs[r * GPITF + q * 4] =
                *(const float4*)(Bm + (size_t)(col0 + r) * K + k0 + q * 4);
        }
        __syncthreads();

#pragma unroll
        for (int kk = 0; kk < 64; kk += 8) {
            unsigned ahi[2][4], alo[2][4];
#pragma unroll
            for (int mt = 0; mt < 2; mt++) {
                int row = warp_m * 32 + mt * 16 + (lane >> 2);
                int c0  = kk + (lane & 3);
                split_tf32(As[row * GPITF + c0],           ahi[mt][0], alo[mt][0]);
                split_tf32(As[(row + 8) * GPITF + c0],     ahi[mt][1], alo[mt][1]);
                split_tf32(As[row * GPITF + c0 + 4],       ahi[mt][2], alo[mt][2]);
                split_tf32(As[(row + 8) * GPITF + c0 + 4], ahi[mt][3], alo[mt][3]);
            }
            unsigned bhi[4][2], blo[4][2];
#pragma unroll
            for (int nt = 0; nt < 4; nt++) {
                int brow = warp_n * 32 + nt * 8 + (lane >> 2);
                int bc   = kk + (lane & 3);
                split_tf32(Bs[brow * GPITF + bc],     bhi[nt][0], blo[nt][0]);
                split_tf32(Bs[brow * GPITF + bc + 4], bhi[nt][1], blo[nt][1]);
            }
#pragma unroll
            for (int mt = 0; mt < 2; mt++)
#pragma unroll
                for (int nt = 0; nt < 4; nt++) {
                    mma_tf32(acc[mt][nt], ahi[mt], bhi[nt]);
                    mma_tf32(acc[mt][nt], ahi[mt], blo[nt]);
                    mma_tf32(acc[mt][nt], alo[mt], bhi[nt]);
                }
        }
        __syncthreads();
    }

#pragma unroll
    for (int mt = 0; mt < 2; mt++)
#pragma unroll
        for (int nt = 0; nt < 4; nt++) {
            int row = row0 + warp_m * 32 + mt * 16 + (lane >> 2);
            int col = col0 + warp_n * 32 + nt * 8 + (lane & 3) * 2;
            float b0 = bias[col], b1 = bias[col + 1];
            *(float2*)(C + (size_t)row * N + col) =
                make_float2(acc[mt][nt][0] + b0, acc[mt][nt][1] + b1);
            *(float2*)(C + (size_t)(row + 8) * N + col) =
                make_float2(acc[mt][nt][2] + b0, acc[mt][nt][3] + b1);
        }
}

// ============================================================================
// LSTM step, 2-product split-tf32: gates ≈ a_hi*(b_hi + b_lo) = a_hi * W.
// A (h_prev) is tf32-rounded (single hi plane; dropped a_lo*W ~ 2^-11.5 rel);
// B (Whh) keeps hi+lo planes. 33% fewer MMAs, 25% less LDS, 66% less A-split
// ALU than R12; otherwise byte-identical structure.
// Grid: 256 CTAs = 128 N-tiles x 2 M-halves. 256 thr = 8 warps:
// 2 warp_m x 4-way K-split; warp tile 32m x 32n.
// Packed col l (0..31): j = ntile*8 + l/4, gate g = l%4 (R7-validated).
// ============================================================================
#define KCS   64
#define PITF  68                      // plane pitch (floats), conflict-free
#define A_PL  (64 * PITF)             // A hi plane: 4352 floats
#define B_PL  (32 * PITF)             // one B plane: 2176 floats
#define STEP_SMEM ((A_PL + 2 * B_PL) * 4)   // 34816 bytes
#define GSM_P (64 * 34)               // one staging partial: 2176 floats

__launch_bounds__(256, 2)
__global__ void lstm_step_tf32(int t,
                               const float* __restrict__ Whh,
                               const float* __restrict__ bhh) {
    const int tid    = threadIdx.x;
    const int lane   = tid & 31;
    const int wid    = tid >> 5;
    const int warp_m = wid >> 2;      // 0..1: m base warp_m*32
    const int ks     = wid & 3;       // 0..3: K-split slice
    const int ntile  = blockIdx.x >> 1;   // 0..127: N-tile
    const int mh     = blockIdx.x & 1;    // 0..1: M-half (rows mh*64..+64)

    float* Ahi = smemf;
    float* Bhi = Ahi + A_PL;
    float* Blo = Bhi + B_PL;
    float* gsm = smemf;               // [4][64][34] partials, reuses planes

    float acc[2][4][4];               // [mt][nt][4]
#pragma unroll
    for (int i = 0; i < 2; i++)
#pragma unroll
        for (int j = 0; j < 4; j++)
#pragma unroll
            for (int k = 0; k < 4; k++) acc[i][j][k] = 0.0f;

    if (t > 0) {
        const float* hprev = g_hs + (size_t)(t - 1) * BATCH * HID + (size_t)mh * 64 * HID;

        // per-thread prefetch registers (chunk granularity)
        float4 rA[4];   // A: 64 rows x 16 float4 = 1024 / 256 thr = 4 each
        float4 rB[2];   // B: 32 rows x 16 float4 = 512 / 256 thr = 2 each
        const int arr[4] = { tid >> 4, (tid + 256) >> 4,
                             (tid + 512) >> 4, (tid + 768) >> 4 };
        const int aq = tid & 15;
        const int brr[2] = { tid >> 4, (tid + 256) >> 4 };
        const int bq = tid & 15;
        int bng[2];
#pragma unroll
        for (int i = 0; i < 2; i++)
            bng[i] = (brr[i] & 3) * HID + ntile * 8 + (brr[i] >> 2);

        // prologue: LDG chunk 0
#pragma unroll
        for (int i = 0; i < 4; i++)
            rA[i] = *(const float4*)(hprev + (size_t)arr[i] * HID + aq * 4);
#pragma unroll
        for (int i = 0; i < 2; i++)
            rB[i] = *(const float4*)(Whh + (size_t)bng[i] * HID + bq * 4);

        for (int c = 0; c < HID / KCS; c++) {
            // ---- stage current chunk: A hi-only, B hi+lo ----
#pragma unroll
            for (int i = 0; i < 4; i++) {
                const float v[4] = { rA[i].x, rA[i].y, rA[i].z, rA[i].w };
                unsigned h4[4];
#pragma unroll
                for (int e = 0; e < 4; e++) h4[e] = cvt_tf32(v[e]);
                *(uint4*)&Ahi[arr[i] * PITF + aq * 4] = make_uint4(h4[0], h4[1], h4[2], h4[3]);
            }
#pragma unroll
            for (int i = 0; i < 2; i++) {
                const float v[4] = { rB[i].x, rB[i].y, rB[i].z, rB[i].w };
                unsigned h4[4], l4[4];
#pragma unroll
                for (int e = 0; e < 4; e++) split_tf32(v[e], h4[e], l4[e]);
                *(uint4*)&Bhi[brr[i] * PITF + bq * 4] = make_uint4(h4[0], h4[1], h4[2], h4[3]);
                *(uint4*)&Blo[brr[i] * PITF + bq * 4] = make_uint4(l4[0], l4[1], l4[2], l4[3]);
            }
            __syncthreads();

            // ---- issue LDG for next chunk (latency hidden by compute) ----
            if (c + 1 < HID / KCS) {
                const int kc = (c + 1) * KCS;
#pragma unroll
                for (int i = 0; i < 4; i++)
                    rA[i] = *(const float4*)(hprev + (size_t)arr[i] * HID + kc + aq * 4);
#pragma unroll
                for (int i = 0; i < 2; i++)
                    rB[i] = *(const float4*)(Whh + (size_t)bng[i] * HID + kc + bq * 4);
            }

            // ---- mainloop: pure LDS + MMA; this warp's 2 kk-steps ----
#pragma unroll
            for (int kk2 = 0; kk2 < 2; kk2++) {
                const int kk = (ks * 2 + kk2) * 8;
                unsigned ahi[2][4], bhi[4][2], blo[4][2];
#pragma unroll
                for (int mt = 0; mt < 2; mt++) {
                    int row = warp_m * 32 + mt * 16 + (lane >> 2);
                    int c0  = kk + (lane & 3);
                    ahi[mt][0] = *(unsigned*)&Ahi[row * PITF + c0];
                    ahi[mt][1] = *(unsigned*)&Ahi[(row + 8) * PITF + c0];
                    ahi[mt][2] = *(unsigned*)&Ahi[row * PITF + c0 + 4];
                    ahi[mt][3] = *(unsigned*)&Ahi[(row + 8) * PITF + c0 + 4];
                }
#pragma unroll
                for (int nt = 0; nt < 4; nt++) {
                    int brow = nt * 8 + (lane >> 2);
                    int bc   = kk + (lane & 3);
                    bhi[nt][0] = *(unsigned*)&Bhi[brow * PITF + bc];
                    bhi[nt][1] = *(unsigned*)&Bhi[brow * PITF + bc + 4];
                    blo[nt][0] = *(unsigned*)&Blo[brow * PITF + bc];
                    blo[nt][1] = *(unsigned*)&Blo[brow * PITF + bc + 4];
                }
#pragma unroll
                for (int mt = 0; mt < 2; mt++)
#pragma unroll
                    for (int nt = 0; nt < 4; nt++) {
                        mma_tf32(acc[mt][nt], ahi[mt], bhi[nt]);
                        mma_tf32(acc[mt][nt], ahi[mt], blo[nt]);
                    }
            }
            __syncthreads();
        }
    }

    // stage K-partial gate pre-activations: gsm[ks][b_loc][l], pitch 34
#pragma unroll
    for (int mt = 0; mt < 2; mt++)
#pragma unroll
        for (int nt = 0; nt < 4; nt++) {
            int row = warp_m * 32 + mt * 16 + (lane >> 2);
            int col = nt * 8 + (lane & 3) * 2;
            *(float2*)(gsm + ks * GSM_P + row * 34 + col) =
                make_float2(acc[mt][nt][0], acc[mt][nt][1]);
            *(float2*)(gsm + ks * GSM_P + (row + 8) * 34 + col) =
                make_float2(acc[mt][nt][2], acc[mt][nt][3]);
        }
    __syncthreads();

    // fused activation epilogue: 512 (b_loc, jj) items / 256 threads
    const float* xp   = g_xproj + (size_t)t * BATCH * G4;
    const float* cin  = g_c[t & 1];
    float*       cout = g_c[(t + 1) & 1];
    float*       hout = g_hs + (size_t)t * BATCH * HID;

#pragma unroll
    for (int it = 0; it < 2; it++) {
        int item  = tid + it * 256;
        int b_loc = item & 63;
        int jj    = item >> 6;          // 0..7
        int b     = mh * 64 + b_loc;
        int j     = ntile * 8 + jj;
        int base  = b_loc * 34 + jj * 4;
        float g0 = 0.f, g1 = 0.f, g2 = 0.f, g3 = 0.f;
#pragma unroll
        for (int p = 0; p < 4; p++) {
            g0 += gsm[p * GSM_P + base + 0];
            g1 += gsm[p * GSM_P + base + 1];
            g2 += gsm[p * GSM_P + base + 2];
            g3 += gsm[p * GSM_P + base + 3];
        }
        size_t xb = (size_t)b * G4 + j;
        float gi = g0 + xp[xb]           + bhh[j];
        float gf = g1 + xp[xb + HID]     + bhh[HID + j];
        float gg = g2 + xp[xb + 2 * HID] + bhh[2 * HID + j];
        float go = g3 + xp[xb + 3 * HID] + bhh[3 * HID + j];
        float cold = (t > 0) ? cin[b * HID + j] : 0.0f;
        float cn = sigmoidf_(gf) * cold + sigmoidf_(gi) * tanhf(gg);
        float hn = sigmoidf_(go) * tanhf(cn);
        cout[b * HID + j] = cn;
        hout[(size_t)b * HID + j] = hn;
    }
}

// ============================================================================
// In-place row-wise log_softmax over 256 columns. One block per row.
// ============================================================================
__launch_bounds__(256)
__global__ void logsoftmax_kernel(float* __restrict__ out) {
    __shared__ float red[256];
    const size_t r = blockIdx.x;
    const int tid  = threadIdx.x;
    float v = out[r * 256 + tid];

    red[tid] = v;
    __syncthreads();
#pragma unroll
    for (int s = 128; s > 0; s >>= 1) {
        if (tid < s) red[tid] = fmaxf(red[tid], red[tid + s]);
        __syncthreads();
    }
    float m = red[0];
    __syncthreads();

    float e = expf(v - m);
    red[tid] = e;
    __syncthreads();
#pragma unroll
    for (int s = 128; s > 0; s >>= 1) {
        if (tid < s) red[tid] += red[tid + s];
        __syncthreads();
    }
    float lse = logf(red[0]) + m;
    out[r * 256 + tid] = v - lse;
}

// ============================================================================
extern "C" void kernel_launch(void* const* d_in, const int* in_sizes, int n_in,
                              void* d_out, int out_size) {
    const float* inp  = (const float*)d_in[0];  // [512,128,256]
    const float* Wxh  = (const float*)d_in[1];  // [4096,256]
    const float* bxh  = (const float*)d_in[2];  // [4096]
    const float* Whh  = (const float*)d_in[3];  // [4096,1024]
    const float* bhh  = (const float*)d_in[4];  // [4096]
    const float* Wout = (const float*)d_in[5];  // [256,1024]
    const float* bout = (const float*)d_in[6];  // [256]
    float* out = (float*)d_out;                 // [512,128,256] fp32

    float* xproj; cudaGetSymbolAddress((void**)&xproj, g_xproj);
    float* hs;    cudaGetSymbolAddress((void**)&hs, g_hs);

    cudaFuncSetAttribute(lstm_step_tf32,
                         cudaFuncAttributeMaxDynamicSharedMemorySize, STEP_SMEM);
    cudaFuncSetAttribute(gemm_tf32,
                         cudaFuncAttributeMaxDynamicSharedMemorySize, GEMM_SMEM);

    // 1) x_proj[T*B, 4H] = inp @ Wxh^T + bxh  (3xTF32)
    gemm_tf32<<<dim3(G4 / 64, TB / 128), 256, GEMM_SMEM>>>(
        inp, Wxh, bxh, xproj, TB, G4, INPD);

    // 2) recurrence (2-product split-tf32, half-M CTAs, 2 CTAs/SM)
    for (int t = 0; t < SEQ; t++)
        lstm_step_tf32<<<256, 256, STEP_SMEM>>>(t, Whh, bhh);

    // 3) out[T*B, 256] = hs @ Wout^T + bout  (3xTF32)
    gemm_tf32<<<dim3(INPD / 64, TB / 128), 256, GEMM_SMEM>>>(
        hs, Wout, bout, out, TB, INPD, HID);

    // 4) log_softmax rows
    logsoftmax_kernel<<<TB, 256>>>(out);
}

// round 15
// speedup vs baseline: 1.8518x; 1.2022x over previous
#include <cuda_runtime.h>
#include <math.h>
#include <stdint.h>

#define SEQ   512
#define BATCH 128
#define INPD  256
#define HID   1024
#define G4    4096
#define TB    (SEQ*BATCH)   // 65536 rows

// ---- scratch (allocation-free: device globals) ----
__device__ float g_xproj[(size_t)TB * G4];   // 1 GiB: [T*B, 4H]
__device__ float g_hs[(size_t)TB * HID];     // 256 MiB: h per timestep (fp32)
__device__ float g_c[2][BATCH * HID];        // ping-pong cell state

__device__ __forceinline__ float sigmoidf_(float x) { return 1.0f / (1.0f + expf(-x)); }

// ============================================================================
// tf32 mma helpers (m16n8k8)
// ============================================================================
__device__ __forceinline__ unsigned cvt_tf32(float x) {
    unsigned r;
    asm("cvt.rna.tf32.f32 %0, %1;" : "=r"(r) : "f"(x));
    return r;
}
__device__ __forceinline__ void split_tf32(float x, unsigned& hi, unsigned& lo) {
    hi = cvt_tf32(x);
    lo = cvt_tf32(x - __uint_as_float(hi));
}
__device__ __forceinline__ void mma_tf32(float* c, const unsigned* a, const unsigned* b) {
    asm volatile("mma.sync.aligned.m16n8k8.row.col.f32.tf32.tf32.f32 "
        "{%0,%1,%2,%3},{%4,%5,%6,%7},{%8,%9},{%0,%1,%2,%3};"
        : "+f"(c[0]), "+f"(c[1]), "+f"(c[2]), "+f"(c[3])
        : "r"(a[0]), "r"(a[1]), "r"(a[2]), "r"(a[3]), "r"(b[0]), "r"(b[1]));
}

extern __shared__ __align__(16) float smemf[];

// ============================================================================
// Generic 3xTF32 GEMM: C[M,N] = A[M,K] * B[N,K]^T + bias[N]  (proven; keeps
// 3 products — xproj errors feed gates directly, keep them tiny)
// ============================================================================
#define GPITF 68
#define GEMM_SMEM ((128 + 64) * GPITF * 4)   // 52224 bytes

__launch_bounds__(256)
__global__ void gemm_tf32(const float* __restrict__ A,
                          const float* __restrict__ Bm,
                          const float* __restrict__ bias,
                          float* __restrict__ C,
                          int M, int N, int K) {
    float* As = smemf;                 // [128][GPITF]
    float* Bs = smemf + 128 * GPITF;   // [64][GPITF]

    const int tid    = threadIdx.x;
    const int lane   = tid & 31;
    const int wid    = tid >> 5;
    const int warp_m = wid >> 1;
    const int warp_n = wid & 1;
    const int row0   = blockIdx.y * 128;
    const int col0   = blockIdx.x * 64;

    float acc[2][4][4];
#pragma unroll
    for (int i = 0; i < 2; i++)
#pragma unroll
        for (int j = 0; j < 4; j++)
#pragma unroll
            for (int k = 0; k < 4; k++) acc[i][j][k] = 0.0f;

    for (int k0 = 0; k0 < K; k0 += 64) {
#pragma unroll
        for (int i = 0; i < 8; i++) {
            int idx = tid + i * 256;
            int r = idx >> 4, q = idx & 15;
            *(float4*)&As[r * GPITF + q * 4] =
                *(const float4*)(A + (size_t)(row0 + r) * K + k0 + q * 4);
        }
#pragma unroll
        for (int i = 0; i < 4; i++) {
            int idx = tid + i * 256;
            int r = idx >> 4, q = idx & 15;
            *(float4*)&Bs[r * GPITF + q * 4] =
                *(const float4*)(Bm + (size_t)(col0 + r) * K + k0 + q * 4);
        }
        __syncthreads();

#pragma unroll
        for (int kk = 0; kk < 64; kk += 8) {
            unsigned ahi[2][4], alo[2][4];
#pragma unroll
            for (int mt = 0; mt < 2; mt++) {
                int row = warp_m * 32 + mt * 16 + (lane >> 2);
                int c0  = kk + (lane & 3);
                split_tf32(As[row * GPITF + c0],           ahi[mt][0], alo[mt][0]);
                split_tf32(As[(row + 8) * GPITF + c0],     ahi[mt][1], alo[mt][1]);
                split_tf32(As[row * GPITF + c0 + 4],       ahi[mt][2], alo[mt][2]);
                split_tf32(As[(row + 8) * GPITF + c0 + 4], ahi[mt][3], alo[mt][3]);
            }
            unsigned bhi[4][2], blo[4][2];
#pragma unroll
            for (int nt = 0; nt < 4; nt++) {
                int brow = warp_n * 32 + nt * 8 + (lane >> 2);
                int bc   = kk + (lane & 3);
                split_tf32(Bs[brow * GPITF + bc],     bhi[nt][0], blo[nt][0]);
                split_tf32(Bs[brow * GPITF + bc + 4], bhi[nt][1], blo[nt][1]);
            }
#pragma unroll
            for (int mt = 0; mt < 2; mt++)
#pragma unroll
                for (int nt = 0; nt < 4; nt++) {
                    mma_tf32(acc[mt][nt], ahi[mt], bhi[nt]);
                    mma_tf32(acc[mt][nt], ahi[mt], blo[nt]);
                    mma_tf32(acc[mt][nt], alo[mt], bhi[nt]);
                }
        }
        __syncthreads();
    }

#pragma unroll
    for (int mt = 0; mt < 2; mt++)
#pragma unroll
        for (int nt = 0; nt < 4; nt++) {
            int row = row0 + warp_m * 32 + mt * 16 + (lane >> 2);
            int col = col0 + warp_n * 32 + nt * 8 + (lane & 3) * 2;
            float b0 = bias[col], b1 = bias[col + 1];
            *(float2*)(C + (size_t)row * N + col) =
                make_float2(acc[mt][nt][0] + b0, acc[mt][nt][1] + b1);
            *(float2*)(C + (size_t)(row + 8) * N + col) =
                make_float2(acc[mt][nt][2] + b0, acc[mt][nt][3] + b1);
        }
}

// ============================================================================
// LSTM step, SINGLE-product tf32: gates ≈ tf32(h) @ tf32(W)^T.
// Calibrated error law (R2 + R13): rel_err ≈ 2.25e-3 * (δW/2^-9) ≈ 2.8e-4.
// Halves MMAs, cuts mainloop LDS 33%, B staging is cvt-only.
// Grid: 256 CTAs = 128 N-tiles x 2 M-halves. 256 thr = 8 warps:
// 2 warp_m x 4-way K-split; warp tile 32m x 32n.
// Packed col l (0..31): j = ntile*8 + l/4, gate g = l%4 (R7-validated).
// NOTE: STEP_SMEM must cover BOTH the plane layout (A_PL + B_PL floats)
// AND the epilogue staging overlay (4 * GSM_P floats) — R14's crash was
// sizing to the planes only.
// ============================================================================
#define KCS   64
#define PITF  68                      // plane pitch (floats), conflict-free
#define A_PL  (64 * PITF)             // A hi plane: 4352 floats
#define B_PL  (32 * PITF)             // B hi plane: 2176 floats
#define GSM_P (64 * 34)               // one staging partial: 2176 floats
#define PLANES_F (A_PL + B_PL)        // 6528 floats
#define STAGE_F  (4 * GSM_P)          // 8704 floats
#define STEP_SMEM (STAGE_F * 4)       // 34816 bytes (> planes: 26112)

__launch_bounds__(256, 2)
__global__ void lstm_step_tf32(int t,
                               const float* __restrict__ Whh,
                               const float* __restrict__ bhh) {
    const int tid    = threadIdx.x;
    const int lane   = tid & 31;
    const int wid    = tid >> 5;
    const int warp_m = wid >> 2;      // 0..1: m base warp_m*32
    const int ks     = wid & 3;       // 0..3: K-split slice
    const int ntile  = blockIdx.x >> 1;   // 0..127: N-tile
    const int mh     = blockIdx.x & 1;    // 0..1: M-half (rows mh*64..+64)

    float* Ahi = smemf;
    float* Bhi = Ahi + A_PL;
    float* gsm = smemf;               // [4][64][34] partials, reuses planes

    float acc[2][4][4];               // [mt][nt][4]
#pragma unroll
    for (int i = 0; i < 2; i++)
#pragma unroll
        for (int j = 0; j < 4; j++)
#pragma unroll
            for (int k = 0; k < 4; k++) acc[i][j][k] = 0.0f;

    if (t > 0) {
        const float* hprev = g_hs + (size_t)(t - 1) * BATCH * HID + (size_t)mh * 64 * HID;

        // per-thread prefetch registers (chunk granularity)
        float4 rA[4];   // A: 64 rows x 16 float4 = 1024 / 256 thr = 4 each
        float4 rB[2];   // B: 32 rows x 16 float4 = 512 / 256 thr = 2 each
        const int arr[4] = { tid >> 4, (tid + 256) >> 4,
                             (tid + 512) >> 4, (tid + 768) >> 4 };
        const int aq = tid & 15;
        const int brr[2] = { tid >> 4, (tid + 256) >> 4 };
        const int bq = tid & 15;
        int bng[2];
#pragma unroll
        for (int i = 0; i < 2; i++)
            bng[i] = (brr[i] & 3) * HID + ntile * 8 + (brr[i] >> 2);

        // prologue: LDG chunk 0
#pragma unroll
        for (int i = 0; i < 4; i++)
            rA[i] = *(const float4*)(hprev + (size_t)arr[i] * HID + aq * 4);
#pragma unroll
        for (int i = 0; i < 2; i++)
            rB[i] = *(const float4*)(Whh + (size_t)bng[i] * HID + bq * 4);

        for (int c = 0; c < HID / KCS; c++) {
            // ---- stage current chunk: A and B hi planes (cvt only) ----
#pragma unroll
            for (int i = 0; i < 4; i++) {
                const float v[4] = { rA[i].x, rA[i].y, rA[i].z, rA[i].w };
                unsigned h4[4];
#pragma unroll
                for (int e = 0; e < 4; e++) h4[e] = cvt_tf32(v[e]);
                *(uint4*)&Ahi[arr[i] * PITF + aq * 4] = make_uint4(h4[0], h4[1], h4[2], h4[3]);
            }
#pragma unroll
            for (int i = 0; i < 2; i++) {
                const float v[4] = { rB[i].x, rB[i].y, rB[i].z, rB[i].w };
                unsigned h4[4];
#pragma unroll
                for (int e = 0; e < 4; e++) h4[e] = cvt_tf32(v[e]);
                *(uint4*)&Bhi[brr[i] * PITF + bq * 4] = make_uint4(h4[0], h4[1], h4[2], h4[3]);
            }
            __syncthreads();

            // ---- issue LDG for next chunk (latency hidden by compute) ----
            if (c + 1 < HID / KCS) {
                const int kc = (c + 1) * KCS;
#pragma unroll
                for (int i = 0; i < 4; i++)
                    rA[i] = *(const float4*)(hprev + (size_t)arr[i] * HID + kc + aq * 4);
#pragma unroll
                for (int i = 0; i < 2; i++)
                    rB[i] = *(const float4*)(Whh + (size_t)bng[i] * HID + kc + bq * 4);
            }

            // ---- mainloop: pure LDS + MMA; this warp's 2 kk-steps ----
#pragma unroll
            for (int kk2 = 0; kk2 < 2; kk2++) {
                const int kk = (ks * 2 + kk2) * 8;
                unsigned ahi[2][4], bhi[4][2];
#pragma unroll
                for (int mt = 0; mt < 2; mt++) {
                    int row = warp_m * 32 + mt * 16 + (lane >> 2);
                    int c0  = kk + (lane & 3);
                    ahi[mt][0] = *(unsigned*)&Ahi[row * PITF + c0];
                    ahi[mt][1] = *(unsigned*)&Ahi[(row + 8) * PITF + c0];
                    ahi[mt][2] = *(unsigned*)&Ahi[row * PITF + c0 + 4];
                    ahi[mt][3] = *(unsigned*)&Ahi[(row + 8) * PITF + c0 + 4];
                }
#pragma unroll
                for (int nt = 0; nt < 4; nt++) {
                    int brow = nt * 8 + (lane >> 2);
                    int bc   = kk + (lane & 3);
                    bhi[nt][0] = *(unsigned*)&Bhi[brow * PITF + bc];
                    bhi[nt][1] = *(unsigned*)&Bhi[brow * PITF + bc + 4];
                }
#pragma unroll
                for (int mt = 0; mt < 2; mt++)
#pragma unroll
                    for (int nt = 0; nt < 4; nt++)
                        mma_tf32(acc[mt][nt], ahi[mt], bhi[nt]);
            }
            __syncthreads();
        }
    }

    // stage K-partial gate pre-activations: gsm[ks][b_loc][l], pitch 34
#pragma unroll
    for (int mt = 0; mt < 2; mt++)
#pragma unroll
        for (int nt = 0; nt < 4; nt++) {
            int row = warp_m * 32 + mt * 16 + (lane >> 2);
            int col = nt * 8 + (lane & 3) * 2;
            *(float2*)(gsm + ks * GSM_P + row * 34 + col) =
                make_float2(acc[mt][nt][0], acc[mt][nt][1]);
            *(float2*)(gsm + ks * GSM_P + (row + 8) * 34 + col) =
                make_float2(acc[mt][nt][2], acc[mt][nt][3]);
        }
    __syncthreads();

    // fused activation epilogue: 512 (b_loc, jj) items / 256 threads
    const float* xp   = g_xproj + (size_t)t * BATCH * G4;
    const float* cin  = g_c[t & 1];
    float*       cout = g_c[(t + 1) & 1];
    float*       hout = g_hs + (size_t)t * BATCH * HID;

#pragma unroll
    for (int it = 0; it < 2; it++) {
        int item  = tid + it * 256;
        int b_loc = item & 63;
        int jj    = item >> 6;          // 0..7
        int b     = mh * 64 + b_loc;
        int j     = ntile * 8 + jj;
        int base  = b_loc * 34 + jj * 4;
        float g0 = 0.f, g1 = 0.f, g2 = 0.f, g3 = 0.f;
#pragma unroll
        for (int p = 0; p < 4; p++) {
            g0 += gsm[p * GSM_P + base + 0];
            g1 += gsm[p * GSM_P + base + 1];
            g2 += gsm[p * GSM_P + base + 2];
            g3 += gsm[p * GSM_P + base + 3];
        }
        size_t xb = (size_t)b * G4 + j;
        float gi = g0 + xp[xb]           + bhh[j];
        float gf = g1 + xp[xb + HID]     + bhh[HID + j];
        float gg = g2 + xp[xb + 2 * HID] + bhh[2 * HID + j];
        float go = g3 + xp[xb + 3 * HID] + bhh[3 * HID + j];
        float cold = (t > 0) ? cin[b * HID + j] : 0.0f;
        float cn = sigmoidf_(gf) * cold + sigmoidf_(gi) * tanhf(gg);
        float hn = sigmoidf_(go) * tanhf(cn);
        cout[b * HID + j] = cn;
        hout[(size_t)b * HID + j] = hn;
    }
}

// ============================================================================
// In-place row-wise log_softmax over 256 columns. One block per row.
// ============================================================================
__launch_bounds__(256)
__global__ void logsoftmax_kernel(float* __restrict__ out) {
    __shared__ float red[256];
    const size_t r = blockIdx.x;
    const int tid  = threadIdx.x;
    float v = out[r * 256 + tid];

    red[tid] = v;
    __syncthreads();
#pragma unroll
    for (int s = 128; s > 0; s >>= 1) {
        if (tid < s) red[tid] = fmaxf(red[tid], red[tid + s]);
        __syncthreads();
    }
    float m = red[0];
    __syncthreads();

    float e = expf(v - m);
    red[tid] = e;
    __syncthreads();
#pragma unroll
    for (int s = 128; s > 0; s >>= 1) {
        if (tid < s) red[tid] += red[tid + s];
        __syncthreads();
    }
    float lse = logf(red[0]) + m;
    out[r * 256 + tid] = v - lse;
}

// ============================================================================
extern "C" void kernel_launch(void* const* d_in, const int* in_sizes, int n_in,
                              void* d_out, int out_size) {
    const float* inp  = (const float*)d_in[0];  // [512,128,256]
    const float* Wxh  = (const float*)d_in[1];  // [4096,256]
    const float* bxh  = (const float*)d_in[2];  // [4096]
    const float* Whh  = (const float*)d_in[3];  // [4096,1024]
    const float* bhh  = (const float*)d_in[4];  // [4096]
    const float* Wout = (const float*)d_in[5];  // [256,1024]
    const float* bout = (const float*)d_in[6];  // [256]
    float* out = (float*)d_out;                 // [512,128,256] fp32

    float* xproj; cudaGetSymbolAddress((void**)&xproj, g_xproj);
    float* hs;    cudaGetSymbolAddress((void**)&hs, g_hs);

    cudaFuncSetAttribute(lstm_step_tf32,
                         cudaFuncAttributeMaxDynamicSharedMemorySize, STEP_SMEM);
    cudaFuncSetAttribute(gemm_tf32,
                         cudaFuncAttributeMaxDynamicSharedMemorySize, GEMM_SMEM);

    // 1) x_proj[T*B, 4H] = inp @ Wxh^T + bxh  (3xTF32, near-exact)
    gemm_tf32<<<dim3(G4 / 64, TB / 128), 256, GEMM_SMEM>>>(
        inp, Wxh, bxh, xproj, TB, G4, INPD);

    // 2) recurrence (single-product tf32, half-M CTAs, 2 CTAs/SM)
    for (int t = 0; t < SEQ; t++)
        lstm_step_tf32<<<256, 256, STEP_SMEM>>>(t, Whh, bhh);

    // 3) out[T*B, 256] = hs @ Wout^T + bout  (3xTF32)
    gemm_tf32<<<dim3(INPD / 64, TB / 128), 256, GEMM_SMEM>>>(
        hs, Wout, bout, out, TB, INPD, HID);

    // 4) log_softmax rows
    logsoftmax_kernel<<<TB, 256>>>(out);
}